// round 10
// baseline (speedup 1.0000x reference)
#include <cuda_runtime.h>
#include <cuda_fp16.h>
#include <cstdint>

// ============================================================================
// BitLinear: out = (rmsnorm(x,gamma) @ ternary(w)^T) * scale
// x [4,2048,2048] f32, w [8192,2048] f32, gamma [2048] f32, out f32.
// GEMM: M=8192, N=8192, K=2048.
//
// NOTE: harness compiles via compute_103 PTX (no 'a' suffix) -> tcgen05/TMA-'a'
// features are REJECTED by ptxas. This kernel uses only baseline PTX:
// cp.async (sm_80), ldmatrix (sm_75), mma.sync.m16n8k16 (sm_80).
// ============================================================================
#define MDIM 8192
#define NDIM 8192
#define KDIM 2048

#define BM 128
#define BN 128
#define BK 64
#define KT (KDIM / BK)          // 32
#define STAGES 3

#define A_STAGE_BYTES (BM * BK * 2)   // 16384
#define B_STAGE_BYTES (BN * BK * 2)   // 16384
#define STAGE_BYTES (A_STAGE_BYTES + B_STAGE_BYTES)   // 32768
#define SMEM_SIZE (STAGES * STAGE_BYTES)              // 98304

// ============================================================================
// Scratch (static device globals — no allocation allowed)
// ============================================================================
__device__ __half g_xn[(size_t)MDIM * KDIM];   // 32 MB rmsnorm(x) fp16
__device__ __half g_wq[(size_t)NDIM * KDIM];   // 32 MB ternary w fp16 (exact)
__device__ float  g_partial[2048];
__device__ float  g_scale;
__device__ float  g_inv_scale;

// ============================================================================
// Preprocessing (deterministic two-stage reductions, no float atomics)
// ============================================================================
__global__ void absmean_partial_kernel(const float* __restrict__ w) {
    __shared__ float sh[8];
    const int tid = threadIdx.x;
    float s = 0.f;
    const float4* w4 = (const float4*)w;
    const int n4 = (NDIM * KDIM) / 4;
    for (int i = blockIdx.x * blockDim.x + tid; i < n4; i += gridDim.x * blockDim.x) {
        float4 v = w4[i];
        s += fabsf(v.x) + fabsf(v.y) + fabsf(v.z) + fabsf(v.w);
    }
    #pragma unroll
    for (int o = 16; o; o >>= 1) s += __shfl_down_sync(0xffffffffu, s, o);
    if ((tid & 31) == 0) sh[tid >> 5] = s;
    __syncthreads();
    if (tid == 0) {
        float t = 0.f;
        #pragma unroll
        for (int i = 0; i < 8; i++) t += sh[i];
        g_partial[blockIdx.x] = t;
    }
}

__global__ void absmean_final_kernel() {
    __shared__ float sh[8];
    const int tid = threadIdx.x;
    float s = 0.f;
    for (int i = tid; i < 2048; i += 256) s += g_partial[i];
    #pragma unroll
    for (int o = 16; o; o >>= 1) s += __shfl_down_sync(0xffffffffu, s, o);
    if ((tid & 31) == 0) sh[tid >> 5] = s;
    __syncthreads();
    if (tid == 0) {
        float t = 0.f;
        #pragma unroll
        for (int i = 0; i < 8; i++) t += sh[i];
        float mean = t * (1.0f / (float)(NDIM * KDIM));
        float sc = fmaxf(mean, 1e-5f);
        g_scale = sc;
        g_inv_scale = 1.0f / sc;
    }
}

__global__ void quantize_kernel(const float* __restrict__ w) {
    const float inv = g_inv_scale;
    const float4* w4 = (const float4*)w;
    uint2* out = (uint2*)g_wq;
    const int n4 = (NDIM * KDIM) / 4;
    for (int i = blockIdx.x * blockDim.x + threadIdx.x; i < n4; i += gridDim.x * blockDim.x) {
        float4 v = w4[i];
        // rintf = round-half-to-even, matches jnp.round
        float q0 = rintf(fminf(fmaxf(v.x * inv, -1.f), 1.f));
        float q1 = rintf(fminf(fmaxf(v.y * inv, -1.f), 1.f));
        float q2 = rintf(fminf(fmaxf(v.z * inv, -1.f), 1.f));
        float q3 = rintf(fminf(fmaxf(v.w * inv, -1.f), 1.f));
        __half2 a = __floats2half2_rn(q0, q1);
        __half2 b = __floats2half2_rn(q2, q3);
        uint2 u;
        u.x = reinterpret_cast<unsigned&>(a);
        u.y = reinterpret_cast<unsigned&>(b);
        out[i] = u;
    }
}

__global__ void rmsnorm_kernel(const float* __restrict__ x, const float* __restrict__ gamma) {
    __shared__ float sh[8];
    __shared__ float s_inv;
    const int row = blockIdx.x;
    const int tid = threadIdx.x;
    const float4* xr = (const float4*)(x + (size_t)row * KDIM);
    float4 v0 = xr[tid];
    float4 v1 = xr[tid + 256];
    float s = v0.x * v0.x + v0.y * v0.y + v0.z * v0.z + v0.w * v0.w
            + v1.x * v1.x + v1.y * v1.y + v1.z * v1.z + v1.w * v1.w;
    #pragma unroll
    for (int o = 16; o; o >>= 1) s += __shfl_down_sync(0xffffffffu, s, o);
    if ((tid & 31) == 0) sh[tid >> 5] = s;
    __syncthreads();
    if (tid == 0) {
        float t = 0.f;
        #pragma unroll
        for (int i = 0; i < 8; i++) t += sh[i];
        s_inv = rsqrtf(t * (1.0f / (float)KDIM) + 1e-5f);
    }
    __syncthreads();
    const float inv = s_inv;
    const float4* g4 = (const float4*)gamma;
    float4 g0 = g4[tid];
    float4 g1 = g4[tid + 256];
    uint2* o = (uint2*)(g_xn + (size_t)row * KDIM);
    __half2 a = __floats2half2_rn(v0.x * inv * g0.x, v0.y * inv * g0.y);
    __half2 b = __floats2half2_rn(v0.z * inv * g0.z, v0.w * inv * g0.w);
    __half2 c = __floats2half2_rn(v1.x * inv * g1.x, v1.y * inv * g1.y);
    __half2 d = __floats2half2_rn(v1.z * inv * g1.z, v1.w * inv * g1.w);
    uint2 u0, u1;
    u0.x = reinterpret_cast<unsigned&>(a);
    u0.y = reinterpret_cast<unsigned&>(b);
    u1.x = reinterpret_cast<unsigned&>(c);
    u1.y = reinterpret_cast<unsigned&>(d);
    o[tid] = u0;
    o[tid + 256] = u1;
}

// ============================================================================
// GEMM helpers
// ============================================================================
__device__ __forceinline__ uint32_t smem_u32(const void* p) {
    uint32_t a;
    asm("{ .reg .u64 t; cvta.to.shared.u64 t, %1; cvt.u32.u64 %0, t; }" : "=r"(a) : "l"(p));
    return a;
}

__device__ __forceinline__ void cp_async16(uint32_t dst, const void* src) {
    asm volatile("cp.async.cg.shared.global [%0], [%1], 16;" :: "r"(dst), "l"(src));
}
__device__ __forceinline__ void cp_commit() {
    asm volatile("cp.async.commit_group;" ::: "memory");
}
template <int N>
__device__ __forceinline__ void cp_wait() {
    asm volatile("cp.async.wait_group %0;" :: "n"(N) : "memory");
}

__device__ __forceinline__ void ldmatrix_x4(uint32_t& r0, uint32_t& r1, uint32_t& r2,
                                            uint32_t& r3, uint32_t addr) {
    asm volatile("ldmatrix.sync.aligned.m8n8.x4.shared.b16 {%0,%1,%2,%3}, [%4];"
                 : "=r"(r0), "=r"(r1), "=r"(r2), "=r"(r3) : "r"(addr));
}

__device__ __forceinline__ void mma16816(float* d, const uint32_t* a, uint32_t b0, uint32_t b1) {
    asm volatile(
        "mma.sync.aligned.m16n8k16.row.col.f32.f16.f16.f32 "
        "{%0,%1,%2,%3}, {%4,%5,%6,%7}, {%8,%9}, {%0,%1,%2,%3};"
        : "+f"(d[0]), "+f"(d[1]), "+f"(d[2]), "+f"(d[3])
        : "r"(a[0]), "r"(a[1]), "r"(a[2]), "r"(a[3]), "r"(b0), "r"(b1));
}

// ============================================================================
// GEMM: out[M,N] = (g_xn[M,K] @ g_wq[N,K]^T) * g_scale
// 256 threads = 8 warps as 4(M) x 2(N); warp tile 32x64.
// Smem tiles 128x64 fp16, rows of 8 16B-chunks, chunk swizzle c ^= (row&7).
// ============================================================================
__global__ void __launch_bounds__(256)
bitlinear_gemm_kernel(float* __restrict__ out) {
    extern __shared__ char smem[];
    const uint32_t sb = smem_u32(smem);
    const int tid = threadIdx.x;
    const int wid = tid >> 5;
    const int lane = tid & 31;
    const int wm = wid >> 1;      // 0..3  -> warp rows  [wm*32, wm*32+32)
    const int wn = wid & 1;       // 0..1  -> warp cols  [wn*64, wn*64+64)

    const int tm = blockIdx.y;    // M tile
    const int tn = blockIdx.x;    // N tile

    const __half* gA = g_xn + (size_t)(tm * BM) * KDIM;
    const __half* gB = g_wq + (size_t)(tn * BN) * KDIM;

    // ---- cp.async addressing: 4 chunks/thread per tile ----
    // chunk id = tid + p*256; row = id>>3, c = id&7
    // dst offset = row*128 + ((c ^ (row&7))<<4); src = row*KDIM + kt*BK + c*8
    uint32_t a_dst[4], b_dst[4];
    size_t a_src[4], b_src[4];
    #pragma unroll
    for (int p = 0; p < 4; p++) {
        int id = tid + p * 256;
        int row = id >> 3, c = id & 7;
        uint32_t off = row * 128 + ((c ^ (row & 7)) << 4);
        a_dst[p] = off;
        b_dst[p] = off;
        a_src[p] = (size_t)row * KDIM + c * 8;
        b_src[p] = (size_t)row * KDIM + c * 8;
    }

    // ---- ldmatrix addressing ----
    // A: row = wm*32 + mi*16 + (lane&15); chunk = ks*2 + (lane>>4), swizzled.
    // B: row = wn*64 + nt*16 + (lane&15); same chunk pattern.
    const int lr = lane & 15;
    const int hs = lane >> 4;
    const int swz_r = lr & 7;   // (row&7) is invariant under +16 steps
    uint32_t a_row_off[2], b_row_off[4], swz[4];
    #pragma unroll
    for (int mi = 0; mi < 2; mi++) a_row_off[mi] = (wm * 32 + mi * 16 + lr) * 128;
    #pragma unroll
    for (int nt = 0; nt < 4; nt++) b_row_off[nt] = (wn * 64 + nt * 16 + lr) * 128;
    #pragma unroll
    for (int ks = 0; ks < 4; ks++) swz[ks] = (uint32_t)(((ks * 2 + hs) ^ swz_r) << 4);

    float acc[2][8][4];
    #pragma unroll
    for (int i = 0; i < 2; i++)
        #pragma unroll
        for (int j = 0; j < 8; j++)
            #pragma unroll
            for (int k = 0; k < 4; k++) acc[i][j][k] = 0.f;

    // ---- prologue: issue stages 0..STAGES-2 ----
    #pragma unroll
    for (int kt = 0; kt < STAGES - 1; kt++) {
        uint32_t sA = sb + kt * STAGE_BYTES;
        uint32_t sBm = sA + A_STAGE_BYTES;
        #pragma unroll
        for (int p = 0; p < 4; p++) {
            cp_async16(sA + a_dst[p], gA + a_src[p] + kt * BK);
            cp_async16(sBm + b_dst[p], gB + b_src[p] + kt * BK);
        }
        cp_commit();
    }

    // ---- mainloop ----
    for (int kt = 0; kt < KT; kt++) {
        cp_wait<STAGES - 2>();
        __syncthreads();

        // prefetch stage kt+STAGES-1 (overwrites stage computed at kt-1)
        int ktn = kt + STAGES - 1;
        if (ktn < KT) {
            int st = ktn % STAGES;
            uint32_t sA = sb + st * STAGE_BYTES;
            uint32_t sBm = sA + A_STAGE_BYTES;
            #pragma unroll
            for (int p = 0; p < 4; p++) {
                cp_async16(sA + a_dst[p], gA + a_src[p] + ktn * BK);
                cp_async16(sBm + b_dst[p], gB + b_src[p] + ktn * BK);
            }
        }
        cp_commit();   // always commit (empty groups keep wait accounting)

        const int st = kt % STAGES;
        const uint32_t sA = sb + st * STAGE_BYTES;
        const uint32_t sBm = sA + A_STAGE_BYTES;

        #pragma unroll
        for (int ks = 0; ks < 4; ks++) {
            uint32_t a[2][4];
            uint32_t b[4][4];
            #pragma unroll
            for (int mi = 0; mi < 2; mi++)
                ldmatrix_x4(a[mi][0], a[mi][1], a[mi][2], a[mi][3],
                            sA + a_row_off[mi] + swz[ks]);
            #pragma unroll
            for (int nt = 0; nt < 4; nt++)
                ldmatrix_x4(b[nt][0], b[nt][1], b[nt][2], b[nt][3],
                            sBm + b_row_off[nt] + swz[ks]);
            #pragma unroll
            for (int mi = 0; mi < 2; mi++)
                #pragma unroll
                for (int nt = 0; nt < 4; nt++) {
                    mma16816(acc[mi][nt * 2 + 0], a[mi], b[nt][0], b[nt][2]);
                    mma16816(acc[mi][nt * 2 + 1], a[mi], b[nt][1], b[nt][3]);
                }
        }
        __syncthreads();
    }

    // ---- epilogue: scale + streaming stores ----
    const float scale = g_scale;
    const int row0 = tm * BM + wm * 32 + (lane >> 2);
    const int col0 = tn * BN + wn * 64 + (lane & 3) * 2;
    #pragma unroll
    for (int mi = 0; mi < 2; mi++) {
        #pragma unroll
        for (int n8 = 0; n8 < 8; n8++) {
            const int r = row0 + mi * 16;
            float* p0 = out + (size_t)r * NDIM + col0 + n8 * 8;
            float* p1 = out + (size_t)(r + 8) * NDIM + col0 + n8 * 8;
            float2 v0 = {acc[mi][n8][0] * scale, acc[mi][n8][1] * scale};
            float2 v1 = {acc[mi][n8][2] * scale, acc[mi][n8][3] * scale};
            __stcs((float2*)p0, v0);
            __stcs((float2*)p1, v1);
        }
    }
}

// ============================================================================
// Host launch
// ============================================================================
extern "C" void kernel_launch(void* const* d_in, const int* in_sizes, int n_in,
                              void* d_out, int out_size) {
    const float* x     = (const float*)d_in[0];
    const float* w     = (const float*)d_in[1];
    const float* gamma = (const float*)d_in[2];
    float* out = (float*)d_out;

    absmean_partial_kernel<<<2048, 256>>>(w);
    absmean_final_kernel<<<1, 256>>>();
    quantize_kernel<<<4096, 256>>>(w);
    rmsnorm_kernel<<<MDIM, 256>>>(x, gamma);

    // unconditional: harness forbids static guards; attribute set is idempotent
    cudaFuncSetAttribute(bitlinear_gemm_kernel,
                         cudaFuncAttributeMaxDynamicSharedMemorySize, SMEM_SIZE);
    dim3 grid(NDIM / BN, MDIM / BM);   // (64, 64)
    bitlinear_gemm_kernel<<<grid, 256, SMEM_SIZE>>>(out);
}

// round 14
// speedup vs baseline: 1.0452x; 1.0452x over previous
#include <cuda_runtime.h>
#include <cuda_fp16.h>
#include <cstdint>

// ============================================================================
// BitLinear: out = (rmsnorm(x,gamma) @ ternary(w)^T) * scale
// GEMM: M=8192, N=8192, K=2048. Baseline-PTX path (no tcgen05 on .target sm_103):
// cp.async + ldmatrix + mma.sync.m16n8k16.
// R10 baseline: 771.8us total (~715us GEMM). R11: slim addressing + 2 CTAs/SM.
// ============================================================================
#define MDIM 8192
#define NDIM 8192
#define KDIM 2048

#define BM 128
#define BN 128
#define BK 64
#define KT (KDIM / BK)          // 32
#define STAGES 3

#define A_STAGE_BYTES (BM * BK * 2)   // 16384
#define B_STAGE_BYTES (BN * BK * 2)   // 16384
#define STAGE_BYTES (A_STAGE_BYTES + B_STAGE_BYTES)   // 32768
#define SMEM_SIZE (STAGES * STAGE_BYTES)              // 98304

// ============================================================================
// Scratch (static device globals — no allocation allowed)
// ============================================================================
__device__ __half g_xn[(size_t)MDIM * KDIM];   // 32 MB rmsnorm(x) fp16
__device__ __half g_wq[(size_t)NDIM * KDIM];   // 32 MB ternary w fp16 (exact)
__device__ float  g_partial[2048];
__device__ float  g_scale;
__device__ float  g_inv_scale;

// ============================================================================
// Preprocessing (deterministic two-stage reductions, no float atomics)
// ============================================================================
__global__ void absmean_partial_kernel(const float* __restrict__ w) {
    __shared__ float sh[8];
    const int tid = threadIdx.x;
    float s = 0.f;
    const float4* w4 = (const float4*)w;
    const int n4 = (NDIM * KDIM) / 4;
    for (int i = blockIdx.x * blockDim.x + tid; i < n4; i += gridDim.x * blockDim.x) {
        float4 v = w4[i];
        s += fabsf(v.x) + fabsf(v.y) + fabsf(v.z) + fabsf(v.w);
    }
    #pragma unroll
    for (int o = 16; o; o >>= 1) s += __shfl_down_sync(0xffffffffu, s, o);
    if ((tid & 31) == 0) sh[tid >> 5] = s;
    __syncthreads();
    if (tid == 0) {
        float t = 0.f;
        #pragma unroll
        for (int i = 0; i < 8; i++) t += sh[i];
        g_partial[blockIdx.x] = t;
    }
}

__global__ void absmean_final_kernel() {
    __shared__ float sh[8];
    const int tid = threadIdx.x;
    float s = 0.f;
    for (int i = tid; i < 2048; i += 256) s += g_partial[i];
    #pragma unroll
    for (int o = 16; o; o >>= 1) s += __shfl_down_sync(0xffffffffu, s, o);
    if ((tid & 31) == 0) sh[tid >> 5] = s;
    __syncthreads();
    if (tid == 0) {
        float t = 0.f;
        #pragma unroll
        for (int i = 0; i < 8; i++) t += sh[i];
        float mean = t * (1.0f / (float)(NDIM * KDIM));
        float sc = fmaxf(mean, 1e-5f);
        g_scale = sc;
        g_inv_scale = 1.0f / sc;
    }
}

__global__ void quantize_kernel(const float* __restrict__ w) {
    const float inv = g_inv_scale;
    const float4* w4 = (const float4*)w;
    uint2* out = (uint2*)g_wq;
    const int n4 = (NDIM * KDIM) / 4;
    for (int i = blockIdx.x * blockDim.x + threadIdx.x; i < n4; i += gridDim.x * blockDim.x) {
        float4 v = w4[i];
        // rintf = round-half-to-even, matches jnp.round
        float q0 = rintf(fminf(fmaxf(v.x * inv, -1.f), 1.f));
        float q1 = rintf(fminf(fmaxf(v.y * inv, -1.f), 1.f));
        float q2 = rintf(fminf(fmaxf(v.z * inv, -1.f), 1.f));
        float q3 = rintf(fminf(fmaxf(v.w * inv, -1.f), 1.f));
        __half2 a = __floats2half2_rn(q0, q1);
        __half2 b = __floats2half2_rn(q2, q3);
        uint2 u;
        u.x = reinterpret_cast<unsigned&>(a);
        u.y = reinterpret_cast<unsigned&>(b);
        out[i] = u;
    }
}

__global__ void rmsnorm_kernel(const float* __restrict__ x, const float* __restrict__ gamma) {
    __shared__ float sh[8];
    __shared__ float s_inv;
    const int row = blockIdx.x;
    const int tid = threadIdx.x;
    const float4* xr = (const float4*)(x + (size_t)row * KDIM);
    float4 v0 = xr[tid];
    float4 v1 = xr[tid + 256];
    float s = v0.x * v0.x + v0.y * v0.y + v0.z * v0.z + v0.w * v0.w
            + v1.x * v1.x + v1.y * v1.y + v1.z * v1.z + v1.w * v1.w;
    #pragma unroll
    for (int o = 16; o; o >>= 1) s += __shfl_down_sync(0xffffffffu, s, o);
    if ((tid & 31) == 0) sh[tid >> 5] = s;
    __syncthreads();
    if (tid == 0) {
        float t = 0.f;
        #pragma unroll
        for (int i = 0; i < 8; i++) t += sh[i];
        s_inv = rsqrtf(t * (1.0f / (float)KDIM) + 1e-5f);
    }
    __syncthreads();
    const float inv = s_inv;
    const float4* g4 = (const float4*)gamma;
    float4 g0 = g4[tid];
    float4 g1 = g4[tid + 256];
    uint2* o = (uint2*)(g_xn + (size_t)row * KDIM);
    __half2 a = __floats2half2_rn(v0.x * inv * g0.x, v0.y * inv * g0.y);
    __half2 b = __floats2half2_rn(v0.z * inv * g0.z, v0.w * inv * g0.w);
    __half2 c = __floats2half2_rn(v1.x * inv * g1.x, v1.y * inv * g1.y);
    __half2 d = __floats2half2_rn(v1.z * inv * g1.z, v1.w * inv * g1.w);
    uint2 u0, u1;
    u0.x = reinterpret_cast<unsigned&>(a);
    u0.y = reinterpret_cast<unsigned&>(b);
    u1.x = reinterpret_cast<unsigned&>(c);
    u1.y = reinterpret_cast<unsigned&>(d);
    o[tid] = u0;
    o[tid + 256] = u1;
}

// ============================================================================
// GEMM helpers
// ============================================================================
__device__ __forceinline__ uint32_t smem_u32(const void* p) {
    uint32_t a;
    asm("{ .reg .u64 t; cvta.to.shared.u64 t, %1; cvt.u32.u64 %0, t; }" : "=r"(a) : "l"(p));
    return a;
}

__device__ __forceinline__ void cp_async16(uint32_t dst, const void* src) {
    asm volatile("cp.async.cg.shared.global [%0], [%1], 16;" :: "r"(dst), "l"(src));
}
__device__ __forceinline__ void cp_commit() {
    asm volatile("cp.async.commit_group;" ::: "memory");
}
template <int N>
__device__ __forceinline__ void cp_wait() {
    asm volatile("cp.async.wait_group %0;" :: "n"(N) : "memory");
}

__device__ __forceinline__ void ldmatrix_x4(uint32_t& r0, uint32_t& r1, uint32_t& r2,
                                            uint32_t& r3, uint32_t addr) {
    asm volatile("ldmatrix.sync.aligned.m8n8.x4.shared.b16 {%0,%1,%2,%3}, [%4];"
                 : "=r"(r0), "=r"(r1), "=r"(r2), "=r"(r3) : "r"(addr));
}

__device__ __forceinline__ void mma16816(float* d, const uint32_t* a, uint32_t b0, uint32_t b1) {
    asm volatile(
        "mma.sync.aligned.m16n8k16.row.col.f32.f16.f16.f32 "
        "{%0,%1,%2,%3}, {%4,%5,%6,%7}, {%8,%9}, {%0,%1,%2,%3};"
        : "+f"(d[0]), "+f"(d[1]), "+f"(d[2]), "+f"(d[3])
        : "r"(a[0]), "r"(a[1]), "r"(a[2]), "r"(a[3]), "r"(b0), "r"(b1));
}

// ============================================================================
// GEMM: out[M,N] = (g_xn[M,K] @ g_wq[N,K]^T) * g_scale
// 256 threads = 8 warps as 4(M) x 2(N); warp tile 32x64.
// Smem tiles 128x64 fp16, rows of 8 16B-chunks, chunk swizzle c ^= (row&7).
// R11: forced 2 CTAs/SM (regs <=128) + scalar cp.async addressing
// (A/B offsets were identical & affine in p: dst+p*4096, src+p*32*KDIM).
// ============================================================================
__global__ void __launch_bounds__(256, 2)
bitlinear_gemm_kernel(float* __restrict__ out) {
    extern __shared__ char smem[];
    const uint32_t sb = smem_u32(smem);
    const int tid = threadIdx.x;
    const int wid = tid >> 5;
    const int lane = tid & 31;
    const int wm = wid >> 1;      // 0..3  -> warp rows  [wm*32, wm*32+32)
    const int wn = wid & 1;       // 0..1  -> warp cols  [wn*64, wn*64+64)

    const int tm = blockIdx.y;    // M tile
    const int tn = blockIdx.x;    // N tile

    const __half* gA = g_xn + (size_t)(tm * BM) * KDIM;
    const __half* gB = g_wq + (size_t)(tn * BN) * KDIM;

    // ---- cp.async addressing: scalar base + affine offsets ----
    // p-th chunk: row = (tid>>3) + 32p, c = tid&7 (row&7 invariant under +32)
    // dst = dst0 + p*4096 ; src = src0 + p*32*KDIM
    const int c_row = tid >> 3;
    const int c_col = tid & 7;
    const uint32_t dst0 = (uint32_t)(c_row * 128 + ((c_col ^ (c_row & 7)) << 4));
    const size_t   src0 = (size_t)c_row * KDIM + c_col * 8;

    // ---- ldmatrix addressing ----
    const int lr = lane & 15;
    const int hs = lane >> 4;
    const int swz_r = lr & 7;   // (row&7) invariant under +16 steps
    uint32_t a_row_off[2], b_row_off[4], swz[4];
    #pragma unroll
    for (int mi = 0; mi < 2; mi++) a_row_off[mi] = (wm * 32 + mi * 16 + lr) * 128;
    #pragma unroll
    for (int nt = 0; nt < 4; nt++) b_row_off[nt] = (wn * 64 + nt * 16 + lr) * 128;
    #pragma unroll
    for (int ks = 0; ks < 4; ks++) swz[ks] = (uint32_t)(((ks * 2 + hs) ^ swz_r) << 4);

    float acc[2][8][4];
    #pragma unroll
    for (int i = 0; i < 2; i++)
        #pragma unroll
        for (int j = 0; j < 8; j++)
            #pragma unroll
            for (int k = 0; k < 4; k++) acc[i][j][k] = 0.f;

    // ---- prologue: issue stages 0..STAGES-2 ----
    #pragma unroll
    for (int kt = 0; kt < STAGES - 1; kt++) {
        uint32_t sA = sb + kt * STAGE_BYTES + dst0;
        uint32_t sBm = sA + A_STAGE_BYTES;
        const __half* pA = gA + src0 + kt * BK;
        const __half* pB = gB + src0 + kt * BK;
        #pragma unroll
        for (int p = 0; p < 4; p++) {
            cp_async16(sA + p * 4096, pA + (size_t)p * (32 * KDIM));
            cp_async16(sBm + p * 4096, pB + (size_t)p * (32 * KDIM));
        }
        cp_commit();
    }

    // ---- mainloop ----
    for (int kt = 0; kt < KT; kt++) {
        cp_wait<STAGES - 2>();
        __syncthreads();

        // prefetch stage kt+STAGES-1
        int ktn = kt + STAGES - 1;
        if (ktn < KT) {
            int st = ktn % STAGES;
            uint32_t sA = sb + st * STAGE_BYTES + dst0;
            uint32_t sBm = sA + A_STAGE_BYTES;
            const __half* pA = gA + src0 + ktn * BK;
            const __half* pB = gB + src0 + ktn * BK;
            #pragma unroll
            for (int p = 0; p < 4; p++) {
                cp_async16(sA + p * 4096, pA + (size_t)p * (32 * KDIM));
                cp_async16(sBm + p * 4096, pB + (size_t)p * (32 * KDIM));
            }
        }
        cp_commit();   // always commit (empty groups keep wait accounting)

        const int st = kt % STAGES;
        const uint32_t sA = sb + st * STAGE_BYTES;
        const uint32_t sBm = sA + A_STAGE_BYTES;

        #pragma unroll
        for (int ks = 0; ks < 4; ks++) {
            uint32_t a[2][4];
            uint32_t b[4][4];
            #pragma unroll
            for (int mi = 0; mi < 2; mi++)
                ldmatrix_x4(a[mi][0], a[mi][1], a[mi][2], a[mi][3],
                            sA + a_row_off[mi] + swz[ks]);
            #pragma unroll
            for (int nt = 0; nt < 4; nt++)
                ldmatrix_x4(b[nt][0], b[nt][1], b[nt][2], b[nt][3],
                            sBm + b_row_off[nt] + swz[ks]);
            #pragma unroll
            for (int mi = 0; mi < 2; mi++)
                #pragma unroll
                for (int nt = 0; nt < 4; nt++) {
                    mma16816(acc[mi][nt * 2 + 0], a[mi], b[nt][0], b[nt][2]);
                    mma16816(acc[mi][nt * 2 + 1], a[mi], b[nt][1], b[nt][3]);
                }
        }
        __syncthreads();
    }

    // ---- epilogue: scale + streaming stores ----
    const float scale = g_scale;
    const int row0 = tm * BM + wm * 32 + (lane >> 2);
    const int col0 = tn * BN + wn * 64 + (lane & 3) * 2;
    #pragma unroll
    for (int mi = 0; mi < 2; mi++) {
        #pragma unroll
        for (int n8 = 0; n8 < 8; n8++) {
            const int r = row0 + mi * 16;
            float* p0 = out + (size_t)r * NDIM + col0 + n8 * 8;
            float* p1 = out + (size_t)(r + 8) * NDIM + col0 + n8 * 8;
            float2 v0 = {acc[mi][n8][0] * scale, acc[mi][n8][1] * scale};
            float2 v1 = {acc[mi][n8][2] * scale, acc[mi][n8][3] * scale};
            __stcs((float2*)p0, v0);
            __stcs((float2*)p1, v1);
        }
    }
}

// ============================================================================
// Host launch
// ============================================================================
extern "C" void kernel_launch(void* const* d_in, const int* in_sizes, int n_in,
                              void* d_out, int out_size) {
    const float* x     = (const float*)d_in[0];
    const float* w     = (const float*)d_in[1];
    const float* gamma = (const float*)d_in[2];
    float* out = (float*)d_out;

    absmean_partial_kernel<<<2048, 256>>>(w);
    absmean_final_kernel<<<1, 256>>>();
    quantize_kernel<<<4096, 256>>>(w);
    rmsnorm_kernel<<<MDIM, 256>>>(x, gamma);

    cudaFuncSetAttribute(bitlinear_gemm_kernel,
                         cudaFuncAttributeMaxDynamicSharedMemorySize, SMEM_SIZE);
    dim3 grid(NDIM / BN, MDIM / BM);   // (64, 64)
    bitlinear_gemm_kernel<<<grid, 256, SMEM_SIZE>>>(out);
}